// round 15
// baseline (speedup 1.0000x reference)
#include <cuda_runtime.h>
#include <cuda_bf16.h>
#include <math.h>
#include <stdint.h>

#define B_ 8
#define T_ 2048
#define C_ 512
#define BT_ (B_*T_)
#define SCALE 0.044194173824159216f

// ---------------- globals ----------------
__device__ __nv_bfloat16 g_Xb[BT_*C_];
__device__ __nv_bfloat16 g_Wb[3*C_*C_];
__device__ __nv_bfloat16 g_Qb[BT_*C_];
__device__ __nv_bfloat16 g_Kb[BT_*C_];
__device__ __nv_bfloat16 g_Vtb[BT_*C_];          // [b][v][t], scaled in-place by 1/colsum
__device__ __nv_bfloat16 g_P[(size_t)B_*T_*T_];  // exp(S*scale) unnormalized; upper tiles stay 0
__device__ float g_csum[BT_];                    // per-(b,i) column sums (atomic)

// ---------------- helpers ----------------
__device__ __forceinline__ uint32_t smem_u32(const void* p) {
    uint32_t a;
    asm("{ .reg .u64 t; cvta.to.shared.u64 t, %1; cvt.u32.u64 %0, t; }" : "=r"(a) : "l"(p));
    return a;
}
__device__ __forceinline__ void cpa(uint32_t dst, const void* src) {
    asm volatile("cp.async.cg.shared.global [%0], [%1], 16;" :: "r"(dst), "l"(src));
}
__device__ __forceinline__ void ldsm4(uint32_t* r, uint32_t a) {
    asm volatile("ldmatrix.sync.aligned.m8n8.x4.shared.b16 {%0,%1,%2,%3}, [%4];"
        : "=r"(r[0]), "=r"(r[1]), "=r"(r[2]), "=r"(r[3]) : "r"(a));
}
__device__ __forceinline__ void mma16816(float* c, const uint32_t* a, const uint32_t* b) {
    asm volatile("mma.sync.aligned.m16n8k16.row.col.f32.bf16.bf16.f32 "
        "{%0,%1,%2,%3}, {%4,%5,%6,%7}, {%8,%9}, {%0,%1,%2,%3};"
        : "+f"(c[0]), "+f"(c[1]), "+f"(c[2]), "+f"(c[3])
        : "r"(a[0]), "r"(a[1]), "r"(a[2]), "r"(a[3]), "r"(b[0]), "r"(b[1]));
}

// smem tile: 128 rows x 64 bf16, row stride 144B (128B data + 16B pad -> conflict-free ldmatrix)
#define RS 144
#define MAT_BYTES (128*RS)        // 18432
#define STAGE_BYTES (2*MAT_BYTES) // 36864
#define NSTAGE 2
#define SMEM_TOT (NSTAGE*STAGE_BYTES)   // 73728 -> 3 CTAs/SM

#define NTHR 128                  // 4 warps; warp tile 64x64, warp grid 2(m) x 2(n)

// load 128x64 bf16 tile gmem->smem via cp.async; src pre-offset (row0,k0); stride elems
__device__ __forceinline__ void ldt64(uint32_t dst, const __nv_bfloat16* src, int stride, int tid) {
    #pragma unroll
    for (int s = 0; s < 8; s++) {
        int slot = tid + s*NTHR;
        int r = slot >> 3, c = slot & 7;
        cpa(dst + r*RS + c*16, (const char*)src + (size_t)r*stride*2 + c*16);
    }
}

// load register fragments for one ks (K=16 slice); warp tile 64x64
__device__ __forceinline__ void load_frags(uint32_t aB, uint32_t bB, int ks, int lane,
                                           int wm, int wn, uint32_t af[4][4], uint32_t bf[8][2]) {
    int ar = wm + (lane & 15);
    int ak = ks*16 + ((lane >> 4) << 3);
    #pragma unroll
    for (int mt = 0; mt < 4; mt++) ldsm4(af[mt], aB + (ar + mt*16)*RS + ak*2);
    int brow = (lane & 7) + ((lane >> 4) & 1) * 8;
    int bk = ks*16 + (((lane >> 3) & 1) << 3);
    #pragma unroll
    for (int ng = 0; ng < 4; ng++) {
        uint32_t r[4];
        ldsm4(r, bB + (wn + ng*16 + brow)*RS + bk*2);
        bf[ng*2+0][0] = r[0]; bf[ng*2+0][1] = r[1];
        bf[ng*2+1][0] = r[2]; bf[ng*2+1][1] = r[3];
    }
}

// one BK=64 chunk: 4 ks steps, register double-buffered fragments; 32 MMAs per ks
__device__ __forceinline__ void compute_chunk(uint32_t aB, uint32_t bB, int lane,
                                              int wm, int wn, float acc[4][8][4]) {
    uint32_t af[2][4][4], bf[2][8][2];
    load_frags(aB, bB, 0, lane, wm, wn, af[0], bf[0]);
    #pragma unroll
    for (int ks = 0; ks < 4; ks++) {
        int cur = ks & 1;
        if (ks < 3) load_frags(aB, bB, ks + 1, lane, wm, wn, af[cur^1], bf[cur^1]);
        #pragma unroll
        for (int mt = 0; mt < 4; mt++)
            #pragma unroll
            for (int nt = 0; nt < 8; nt++)
                mma16816(acc[mt][nt], af[cur][mt], bf[cur][nt]);
    }
}

// 2-stage pipelined GEMM over BK=64 chunks; single sync per chunk.
// Order per iter: wait(chunk k) -> sync -> issue loads(chunk k+1, stage cs^1) -> compute(cs).
template<class F>
__device__ __forceinline__ void gemm_pipe(float acc[4][8][4], int nk, int tid,
                                          int lane, int wm, int wn, F load) {
    extern __shared__ __align__(16) char smbuf[];
    uint32_t sb = smem_u32(smbuf);
    #pragma unroll
    for (int mt = 0; mt < 4; mt++)
        #pragma unroll
        for (int nt = 0; nt < 8; nt++)
            #pragma unroll
            for (int c = 0; c < 4; c++) acc[mt][nt][c] = 0.f;

    load(sb, sb + MAT_BYTES, 0);
    asm volatile("cp.async.commit_group;" ::: "memory");
    int cs = 0;
    for (int k = 0; k < nk; k++) {
        asm volatile("cp.async.wait_group 0;" ::: "memory");
        __syncthreads();
        if (k + 1 < nk) {
            uint32_t st = sb + (cs^1)*STAGE_BYTES;
            load(st, st + MAT_BYTES, k + 1);
            asm volatile("cp.async.commit_group;" ::: "memory");
        }
        uint32_t st = sb + cs*STAGE_BYTES;
        compute_chunk(st, st + MAT_BYTES, lane, wm, wn, acc);
        cs ^= 1;
    }
}

// ---- fused prep: X fp32 -> (out left half via streaming store, bf16 Xb); W -> bf16; zero csum ----
__global__ __launch_bounds__(256) void prep_k(const float* __restrict__ X,
                                              float* __restrict__ out,
                                              __nv_bfloat16* __restrict__ dstX,
                                              const float* __restrict__ Wq,
                                              const float* __restrict__ Wk,
                                              const float* __restrict__ Wv,
                                              __nv_bfloat16* __restrict__ dstW) {
    int bx = blockIdx.x;
    if (bx < 8192) {
        if (bx < 16)
            ((float4*)g_csum)[bx * 256 + threadIdx.x] = make_float4(0.f, 0.f, 0.f, 0.f);
        int g = bx * 256 + threadIdx.x;
        float4 v = ((const float4*)X)[g];
        int row = g >> 7, c4 = g & 127;
        __stcs(((float4*)out) + ((size_t)row * 256 + c4), v);   // never re-read: evict-first
        __nv_bfloat162 a = __floats2bfloat162_rn(v.x, v.y);
        __nv_bfloat162 b = __floats2bfloat162_rn(v.z, v.w);
        uint2 o; o.x = *(uint32_t*)&a; o.y = *(uint32_t*)&b;
        ((uint2*)dstX)[g] = o;
    } else {
        int w = bx - 8192;                 // 0..767 : 256 blocks per weight matrix
        int z = w >> 8;
        const float* src = (z == 0) ? Wq : (z == 1) ? Wk : Wv;
        int g = (w & 255) * 256 + threadIdx.x;
        float4 v = ((const float4*)src)[g];
        __nv_bfloat162 a = __floats2bfloat162_rn(v.x, v.y);
        __nv_bfloat162 b = __floats2bfloat162_rn(v.z, v.w);
        uint2 o; o.x = *(uint32_t*)&a; o.y = *(uint32_t*)&b;
        ((uint2*)(dstW + (size_t)z * C_ * C_))[g] = o;
    }
}

// ---------------- QKV projection ----------------
__global__ __launch_bounds__(NTHR, 3) void qkv_t(const float* __restrict__ bq,
                                                 const float* __restrict__ bk,
                                                 const float* __restrict__ bv) {
    extern __shared__ __align__(16) char smbuf[];
    const int tid = threadIdx.x, wid = tid >> 5, lane = tid & 31;
    const int wm = (wid >> 1) * 64, wn = (wid & 1) * 64;
    const int z = blockIdx.z, m0 = blockIdx.y * 128, n0 = blockIdx.x * 128;
    const __nv_bfloat16* A  = g_Xb + (size_t)m0 * C_;
    const __nv_bfloat16* Bm = g_Wb + (size_t)z * C_ * C_ + (size_t)n0 * C_;
    const float* bias = (z == 0) ? bq : (z == 1) ? bk : bv;

    float acc[4][8][4];
    gemm_pipe(acc, C_/64, tid, lane, wm, wn, [=](uint32_t ad, uint32_t bd, int k) {
        ldt64(ad, A  + k*64, C_, tid);
        ldt64(bd, Bm + k*64, C_, tid);
    });

    const int gid = lane >> 2, tig = lane & 3;
    if (z < 2) {
        __nv_bfloat16* Dst = (z == 0) ? g_Qb : g_Kb;
        #pragma unroll
        for (int mt = 0; mt < 4; mt++)
            #pragma unroll
            for (int nt = 0; nt < 8; nt++)
                #pragma unroll
                for (int h = 0; h < 2; h++) {
                    int m = m0 + wm + mt*16 + gid + h*8;
                    int n = n0 + wn + nt*8 + tig*2;
                    float v0 = acc[mt][nt][h*2+0] + __ldg(bias + n);
                    float v1 = acc[mt][nt][h*2+1] + __ldg(bias + n + 1);
                    __nv_bfloat162 p = __floats2bfloat162_rn(v0, v1);
                    *(uint32_t*)(Dst + (size_t)m * C_ + n) = *(uint32_t*)&p;
                }
    } else {
        // V: transpose via smem (pipeline buffer is free), then coalesced row writes
        __syncthreads();
        __nv_bfloat16* ts = (__nv_bfloat16*)smbuf;   // [128 v][136 t] bf16
        #pragma unroll
        for (int mt = 0; mt < 4; mt++)
            #pragma unroll
            for (int nt = 0; nt < 8; nt++)
                #pragma unroll
                for (int h = 0; h < 2; h++) {
                    int mm = wm + mt*16 + gid + h*8;
                    int nn = wn + nt*8 + tig*2;
                    float v0 = acc[mt][nt][h*2+0] + __ldg(bias + n0 + nn);
                    float v1 = acc[mt][nt][h*2+1] + __ldg(bias + n0 + nn + 1);
                    ts[nn*136 + mm]       = __float2bfloat16_rn(v0);
                    ts[(nn+1)*136 + mm]   = __float2bfloat16_rn(v1);
                }
        __syncthreads();
        int bb = m0 >> 11, t0 = m0 & (T_ - 1);
        int r = tid;                                  // 128 threads, one Vt row each
        const uint4* src = (const uint4*)(ts + r*136);
        uint4* dst = (uint4*)(g_Vtb + ((size_t)bb * C_ + n0 + r) * T_ + t0);
        #pragma unroll
        for (int c = 0; c < 16; c++) dst[c] = src[c];
    }
}

// ---------------- logits -> unnormalized exp probs (bf16) + fused column sums ----
__global__ __launch_bounds__(NTHR, 3) void logits_t() {
    const int tid = threadIdx.x, wid = tid >> 5, lane = tid & 31;
    const int wm = (wid >> 1) * 64, wn = (wid & 1) * 64;
    const int b = blockIdx.y;
    int x = blockIdx.x;
    int jt = (int)((sqrtf(8.f*x + 1.f) - 1.f) * 0.5f);
    while ((jt + 1)*(jt + 2)/2 <= x) jt++;
    while (jt*(jt + 1)/2 > x) jt--;
    const int it = x - jt*(jt + 1)/2;
    const int m0 = jt * 128, n0 = it * 128;
    const __nv_bfloat16* Q = g_Qb + (size_t)b*T_*C_ + (size_t)m0 * C_;
    const __nv_bfloat16* K = g_Kb + (size_t)b*T_*C_ + (size_t)n0 * C_;

    float acc[4][8][4];
    gemm_pipe(acc, C_/64, tid, lane, wm, wn, [=](uint32_t ad, uint32_t bd, int k) {
        ldt64(ad, Q + k*64, C_, tid);
        ldt64(bd, K + k*64, C_, tid);
    });

    const int gid = lane >> 2, tig = lane & 3;
    __nv_bfloat16* Pb = g_P + (size_t)b*T_*T_;
    #pragma unroll
    for (int nt = 0; nt < 8; nt++) {
        float cs0 = 0.f, cs1 = 0.f;
        #pragma unroll
        for (int mt = 0; mt < 4; mt++)
            #pragma unroll
            for (int h = 0; h < 2; h++) {
                int j = m0 + wm + mt*16 + gid + h*8;
                int i = n0 + wn + nt*8 + tig*2;
                float e0 = (i+0 > j) ? 0.f : __expf(acc[mt][nt][h*2+0] * SCALE);
                float e1 = (i+1 > j) ? 0.f : __expf(acc[mt][nt][h*2+1] * SCALE);
                __nv_bfloat162 p = __floats2bfloat162_rn(e0, e1);
                *(uint32_t*)(Pb + (size_t)j * T_ + i) = *(uint32_t*)&p;
                cs0 += __low2float(p);
                cs1 += __high2float(p);
            }
        float s0 = cs0, s1 = cs1;
        s0 += __shfl_down_sync(0xffffffffu, s0, 16);
        s0 += __shfl_down_sync(0xffffffffu, s0, 8);
        s0 += __shfl_down_sync(0xffffffffu, s0, 4);
        s1 += __shfl_down_sync(0xffffffffu, s1, 16);
        s1 += __shfl_down_sync(0xffffffffu, s1, 8);
        s1 += __shfl_down_sync(0xffffffffu, s1, 4);
        if (gid == 0) {
            int i = n0 + wn + nt*8 + tig*2;
            atomicAdd(&g_csum[b*T_ + i],     s0);
            atomicAdd(&g_csum[b*T_ + i + 1], s1);
        }
    }
}

// ---------------- scale Vt rows by 1/colsum ----------------
__global__ __launch_bounds__(256) void scalev_k() {
    int g = blockIdx.x * 256 + threadIdx.x;
    int o = g * 2;
    int b = o >> 20, i = o & (T_ - 1);
    __nv_bfloat162 v = ((__nv_bfloat162*)g_Vtb)[g];
    float2 f = __bfloat1622float2(v);
    f.x *= 1.0f / g_csum[b*T_ + i];
    f.y *= 1.0f / g_csum[b*T_ + i + 1];
    ((__nv_bfloat162*)g_Vtb)[g] = __floats2bfloat162_rn(f.x, f.y);
}

// ---------------- read = P @ Vs^T (longest-first scheduling) ----------------
__global__ __launch_bounds__(NTHR, 3) void read_t(float* __restrict__ out) {
    const int tid = threadIdx.x, wid = tid >> 5, lane = tid & 31;
    const int wm = (wid >> 1) * 64, wn = (wid & 1) * 64;
    const int b = blockIdx.z;
    const int jt = 15 - blockIdx.y;                  // longest CTAs dispatch first
    const int m0 = jt * 128, n0 = blockIdx.x * 128;
    const int nk = 2 * (jt + 1);                     // BK=64 chunks; P zero beyond diag
    const __nv_bfloat16* P = g_P   + (size_t)b*T_*T_ + (size_t)m0 * T_;
    const __nv_bfloat16* V = g_Vtb + (size_t)b*C_*T_ + (size_t)n0 * T_;

    float acc[4][8][4];
    gemm_pipe(acc, nk, tid, lane, wm, wn, [=](uint32_t ad, uint32_t bd, int k) {
        ldt64(ad, P + k*64, T_, tid);
        ldt64(bd, V + k*64, T_, tid);
    });

    const int gid = lane >> 2, tig = lane & 3;
    #pragma unroll
    for (int mt = 0; mt < 4; mt++)
        #pragma unroll
        for (int nt = 0; nt < 8; nt++)
            #pragma unroll
            for (int h = 0; h < 2; h++) {
                int m = m0 + wm + mt*16 + gid + h*8;
                int n = n0 + wn + nt*8 + tig*2;
                float* orow = out + ((size_t)b * T_ + m) * 1024 + 512;
                *(float2*)(orow + n) = make_float2(acc[mt][nt][h*2+0], acc[mt][nt][h*2+1]);
            }
}

// ---------------------------------------------------------------------------
extern "C" void kernel_launch(void* const* d_in, const int* in_sizes, int n_in,
                              void* d_out, int out_size)
{
    const float* X  = (const float*)d_in[0];
    const float* Wq = (const float*)d_in[1];
    const float* bq = (const float*)d_in[2];
    const float* Wk = (const float*)d_in[3];
    const float* bk = (const float*)d_in[4];
    const float* Wv = (const float*)d_in[5];
    const float* bv = (const float*)d_in[6];
    float* out = (float*)d_out;

    cudaFuncSetAttribute(qkv_t,    cudaFuncAttributeMaxDynamicSharedMemorySize, SMEM_TOT);
    cudaFuncSetAttribute(logits_t, cudaFuncAttributeMaxDynamicSharedMemorySize, SMEM_TOT);
    cudaFuncSetAttribute(read_t,   cudaFuncAttributeMaxDynamicSharedMemorySize, SMEM_TOT);

    __nv_bfloat16* Xb; cudaGetSymbolAddress((void**)&Xb, g_Xb);
    __nv_bfloat16* Wb; cudaGetSymbolAddress((void**)&Wb, g_Wb);

    prep_k<<<8960, 256>>>(X, out, Xb, Wq, Wk, Wv, Wb);
    qkv_t<<<dim3(4, 128, 3), NTHR, SMEM_TOT>>>(bq, bk, bv);
    logits_t<<<dim3(136, 8), NTHR, SMEM_TOT>>>();
    scalev_k<<<16384, 256>>>();
    read_t<<<dim3(4, 16, 8), NTHR, SMEM_TOT>>>(out);
}

// round 16
// speedup vs baseline: 1.4986x; 1.4986x over previous
#include <cuda_runtime.h>
#include <cuda_bf16.h>
#include <math.h>
#include <stdint.h>

#define B_ 8
#define T_ 2048
#define C_ 512
#define BT_ (B_*T_)
#define SCALE 0.044194173824159216f

// ---------------- globals ----------------
__device__ __nv_bfloat16 g_Xb[BT_*C_];
__device__ __nv_bfloat16 g_Wb[3*C_*C_];
__device__ __nv_bfloat16 g_Qb[BT_*C_];
__device__ __nv_bfloat16 g_Kb[BT_*C_];
__device__ __nv_bfloat16 g_Vtb[BT_*C_];          // [b][v][t], scaled in-place by 1/colsum
__device__ __nv_bfloat16 g_P[(size_t)B_*T_*T_];  // exp(S*scale) unnormalized; upper tiles stay 0
__device__ float g_csum[BT_];                    // per-(b,i) column sums (atomic)

// ---------------- helpers ----------------
__device__ __forceinline__ uint32_t smem_u32(const void* p) {
    uint32_t a;
    asm("{ .reg .u64 t; cvta.to.shared.u64 t, %1; cvt.u32.u64 %0, t; }" : "=r"(a) : "l"(p));
    return a;
}
__device__ __forceinline__ void cpa(uint32_t dst, const void* src) {
    asm volatile("cp.async.cg.shared.global [%0], [%1], 16;" :: "r"(dst), "l"(src));
}
__device__ __forceinline__ void ldsm4(uint32_t* r, uint32_t a) {
    asm volatile("ldmatrix.sync.aligned.m8n8.x4.shared.b16 {%0,%1,%2,%3}, [%4];"
        : "=r"(r[0]), "=r"(r[1]), "=r"(r[2]), "=r"(r[3]) : "r"(a));
}
__device__ __forceinline__ void mma16816(float* c, const uint32_t* a, const uint32_t* b) {
    asm volatile("mma.sync.aligned.m16n8k16.row.col.f32.bf16.bf16.f32 "
        "{%0,%1,%2,%3}, {%4,%5,%6,%7}, {%8,%9}, {%0,%1,%2,%3};"
        : "+f"(c[0]), "+f"(c[1]), "+f"(c[2]), "+f"(c[3])
        : "r"(a[0]), "r"(a[1]), "r"(a[2]), "r"(a[3]), "r"(b[0]), "r"(b[1]));
}

// smem tile: 128 rows x 64 bf16, row stride 144B (128B data + 16B pad -> conflict-free ldmatrix)
#define RS 144
#define MAT_BYTES (128*RS)        // 18432
#define STAGE_BYTES (2*MAT_BYTES) // 36864
#define NSTAGE 2
#define SMEM_TOT (NSTAGE*STAGE_BYTES)   // 73728 -> 3 CTAs/SM

#define NTHR 128                  // 4 warps; warp tile 64x64, warp grid 2(m) x 2(n)

// load 128x64 bf16 tile gmem->smem via cp.async; src pre-offset (row0,k0); stride elems
__device__ __forceinline__ void ldt64(uint32_t dst, const __nv_bfloat16* src, int stride, int tid) {
    #pragma unroll
    for (int s = 0; s < 8; s++) {
        int slot = tid + s*NTHR;
        int r = slot >> 3, c = slot & 7;
        cpa(dst + r*RS + c*16, (const char*)src + (size_t)r*stride*2 + c*16);
    }
}

// load register fragments for one ks (K=16 slice); warp tile 64x64
__device__ __forceinline__ void load_frags(uint32_t aB, uint32_t bB, int ks, int lane,
                                           int wm, int wn, uint32_t af[4][4], uint32_t bf[8][2]) {
    int ar = wm + (lane & 15);
    int ak = ks*16 + ((lane >> 4) << 3);
    #pragma unroll
    for (int mt = 0; mt < 4; mt++) ldsm4(af[mt], aB + (ar + mt*16)*RS + ak*2);
    int brow = (lane & 7) + ((lane >> 4) & 1) * 8;
    int bk = ks*16 + (((lane >> 3) & 1) << 3);
    #pragma unroll
    for (int ng = 0; ng < 4; ng++) {
        uint32_t r[4];
        ldsm4(r, bB + (wn + ng*16 + brow)*RS + bk*2);
        bf[ng*2+0][0] = r[0]; bf[ng*2+0][1] = r[1];
        bf[ng*2+1][0] = r[2]; bf[ng*2+1][1] = r[3];
    }
}

// one BK=64 chunk: 4 ks steps, register double-buffered fragments; 32 MMAs per ks
__device__ __forceinline__ void compute_chunk(uint32_t aB, uint32_t bB, int lane,
                                              int wm, int wn, float acc[4][8][4]) {
    uint32_t af[2][4][4], bf[2][8][2];
    load_frags(aB, bB, 0, lane, wm, wn, af[0], bf[0]);
    #pragma unroll
    for (int ks = 0; ks < 4; ks++) {
        int cur = ks & 1;
        if (ks < 3) load_frags(aB, bB, ks + 1, lane, wm, wn, af[cur^1], bf[cur^1]);
        #pragma unroll
        for (int mt = 0; mt < 4; mt++)
            #pragma unroll
            for (int nt = 0; nt < 8; nt++)
                mma16816(acc[mt][nt], af[cur][mt], bf[cur][nt]);
    }
}

// 2-stage pipelined GEMM over BK=64 chunks; single sync per chunk.
// Order per iter: wait(chunk k) -> sync -> issue loads(chunk k+1, stage cs^1) -> compute(cs).
template<class F>
__device__ __forceinline__ void gemm_pipe(float acc[4][8][4], int nk, int tid,
                                          int lane, int wm, int wn, F load) {
    extern __shared__ __align__(16) char smbuf[];
    uint32_t sb = smem_u32(smbuf);
    #pragma unroll
    for (int mt = 0; mt < 4; mt++)
        #pragma unroll
        for (int nt = 0; nt < 8; nt++)
            #pragma unroll
            for (int c = 0; c < 4; c++) acc[mt][nt][c] = 0.f;

    load(sb, sb + MAT_BYTES, 0);
    asm volatile("cp.async.commit_group;" ::: "memory");
    int cs = 0;
    for (int k = 0; k < nk; k++) {
        asm volatile("cp.async.wait_group 0;" ::: "memory");
        __syncthreads();
        if (k + 1 < nk) {
            uint32_t st = sb + (cs^1)*STAGE_BYTES;
            load(st, st + MAT_BYTES, k + 1);
            asm volatile("cp.async.commit_group;" ::: "memory");
        }
        uint32_t st = sb + cs*STAGE_BYTES;
        compute_chunk(st, st + MAT_BYTES, lane, wm, wn, acc);
        cs ^= 1;
    }
}

// ---------------- fused: X fp32 -> (out left half, bf16 Xb); first blocks zero csum ----
__global__ __launch_bounds__(256) void xprep_k(const float* __restrict__ X,
                                               float* __restrict__ out,
                                               __nv_bfloat16* __restrict__ dst) {
    if (blockIdx.x < 16)
        ((float4*)g_csum)[blockIdx.x * 256 + threadIdx.x] = make_float4(0.f, 0.f, 0.f, 0.f);
    int g = blockIdx.x * 256 + threadIdx.x;
    float4 v = ((const float4*)X)[g];
    int row = g >> 7, c4 = g & 127;
    ((float4*)out)[(size_t)row * 256 + c4] = v;
    __nv_bfloat162 a = __floats2bfloat162_rn(v.x, v.y);
    __nv_bfloat162 b = __floats2bfloat162_rn(v.z, v.w);
    uint2 o; o.x = *(uint32_t*)&a; o.y = *(uint32_t*)&b;
    ((uint2*)dst)[g] = o;
}

// ---------------- weights fp32 -> bf16 ----------------
__global__ __launch_bounds__(256) void wprep_k(const float* __restrict__ Wq,
                                               const float* __restrict__ Wk,
                                               const float* __restrict__ Wv,
                                               __nv_bfloat16* __restrict__ dst) {
    int z = blockIdx.y;
    const float* src = (z == 0) ? Wq : (z == 1) ? Wk : Wv;
    int g = blockIdx.x * 256 + threadIdx.x;
    float4 v = ((const float4*)src)[g];
    __nv_bfloat162 a = __floats2bfloat162_rn(v.x, v.y);
    __nv_bfloat162 b = __floats2bfloat162_rn(v.z, v.w);
    uint2 o; o.x = *(uint32_t*)&a; o.y = *(uint32_t*)&b;
    ((uint2*)(dst + (size_t)z * C_ * C_))[g] = o;
}

// ---------------- QKV projection ----------------
__global__ __launch_bounds__(NTHR, 3) void qkv_t(const float* __restrict__ bq,
                                                 const float* __restrict__ bk,
                                                 const float* __restrict__ bv) {
    extern __shared__ __align__(16) char smbuf[];
    const int tid = threadIdx.x, wid = tid >> 5, lane = tid & 31;
    const int wm = (wid >> 1) * 64, wn = (wid & 1) * 64;
    const int z = blockIdx.z, m0 = blockIdx.y * 128, n0 = blockIdx.x * 128;
    const __nv_bfloat16* A  = g_Xb + (size_t)m0 * C_;
    const __nv_bfloat16* Bm = g_Wb + (size_t)z * C_ * C_ + (size_t)n0 * C_;
    const float* bias = (z == 0) ? bq : (z == 1) ? bk : bv;

    float acc[4][8][4];
    gemm_pipe(acc, C_/64, tid, lane, wm, wn, [=](uint32_t ad, uint32_t bd, int k) {
        ldt64(ad, A  + k*64, C_, tid);
        ldt64(bd, Bm + k*64, C_, tid);
    });

    const int gid = lane >> 2, tig = lane & 3;
    if (z < 2) {
        __nv_bfloat16* Dst = (z == 0) ? g_Qb : g_Kb;
        #pragma unroll
        for (int mt = 0; mt < 4; mt++)
            #pragma unroll
            for (int nt = 0; nt < 8; nt++)
                #pragma unroll
                for (int h = 0; h < 2; h++) {
                    int m = m0 + wm + mt*16 + gid + h*8;
                    int n = n0 + wn + nt*8 + tig*2;
                    float v0 = acc[mt][nt][h*2+0] + __ldg(bias + n);
                    float v1 = acc[mt][nt][h*2+1] + __ldg(bias + n + 1);
                    __nv_bfloat162 p = __floats2bfloat162_rn(v0, v1);
                    *(uint32_t*)(Dst + (size_t)m * C_ + n) = *(uint32_t*)&p;
                }
    } else {
        // V: transpose via smem (pipeline buffer is free), then coalesced row writes
        __syncthreads();
        __nv_bfloat16* ts = (__nv_bfloat16*)smbuf;   // [128 v][136 t] bf16
        #pragma unroll
        for (int mt = 0; mt < 4; mt++)
            #pragma unroll
            for (int nt = 0; nt < 8; nt++)
                #pragma unroll
                for (int h = 0; h < 2; h++) {
                    int mm = wm + mt*16 + gid + h*8;
                    int nn = wn + nt*8 + tig*2;
                    float v0 = acc[mt][nt][h*2+0] + __ldg(bias + n0 + nn);
                    float v1 = acc[mt][nt][h*2+1] + __ldg(bias + n0 + nn + 1);
                    ts[nn*136 + mm]       = __float2bfloat16_rn(v0);
                    ts[(nn+1)*136 + mm]   = __float2bfloat16_rn(v1);
                }
        __syncthreads();
        int bb = m0 >> 11, t0 = m0 & (T_ - 1);
        int r = tid;                                  // 128 threads, one Vt row each
        const uint4* src = (const uint4*)(ts + r*136);
        uint4* dst = (uint4*)(g_Vtb + ((size_t)bb * C_ + n0 + r) * T_ + t0);
        #pragma unroll
        for (int c = 0; c < 16; c++) dst[c] = src[c];
    }
}

// ---------------- logits -> unnormalized exp probs (bf16) + fused column sums ----
__global__ __launch_bounds__(NTHR, 3) void logits_t() {
    const int tid = threadIdx.x, wid = tid >> 5, lane = tid & 31;
    const int wm = (wid >> 1) * 64, wn = (wid & 1) * 64;
    const int b = blockIdx.y;
    int x = blockIdx.x;
    int jt = (int)((sqrtf(8.f*x + 1.f) - 1.f) * 0.5f);
    while ((jt + 1)*(jt + 2)/2 <= x) jt++;
    while (jt*(jt + 1)/2 > x) jt--;
    const int it = x - jt*(jt + 1)/2;
    const int m0 = jt * 128, n0 = it * 128;
    const __nv_bfloat16* Q = g_Qb + (size_t)b*T_*C_ + (size_t)m0 * C_;
    const __nv_bfloat16* K = g_Kb + (size_t)b*T_*C_ + (size_t)n0 * C_;

    float acc[4][8][4];
    gemm_pipe(acc, C_/64, tid, lane, wm, wn, [=](uint32_t ad, uint32_t bd, int k) {
        ldt64(ad, Q + k*64, C_, tid);
        ldt64(bd, K + k*64, C_, tid);
    });

    const int gid = lane >> 2, tig = lane & 3;
    __nv_bfloat16* Pb = g_P + (size_t)b*T_*T_;
    #pragma unroll
    for (int nt = 0; nt < 8; nt++) {
        float cs0 = 0.f, cs1 = 0.f;
        #pragma unroll
        for (int mt = 0; mt < 4; mt++)
            #pragma unroll
            for (int h = 0; h < 2; h++) {
                int j = m0 + wm + mt*16 + gid + h*8;
                int i = n0 + wn + nt*8 + tig*2;
                float e0 = (i+0 > j) ? 0.f : __expf(acc[mt][nt][h*2+0] * SCALE);
                float e1 = (i+1 > j) ? 0.f : __expf(acc[mt][nt][h*2+1] * SCALE);
                __nv_bfloat162 p = __floats2bfloat162_rn(e0, e1);
                *(uint32_t*)(Pb + (size_t)j * T_ + i) = *(uint32_t*)&p;
                cs0 += __low2float(p);
                cs1 += __high2float(p);
            }
        float s0 = cs0, s1 = cs1;
        s0 += __shfl_down_sync(0xffffffffu, s0, 16);
        s0 += __shfl_down_sync(0xffffffffu, s0, 8);
        s0 += __shfl_down_sync(0xffffffffu, s0, 4);
        s1 += __shfl_down_sync(0xffffffffu, s1, 16);
        s1 += __shfl_down_sync(0xffffffffu, s1, 8);
        s1 += __shfl_down_sync(0xffffffffu, s1, 4);
        if (gid == 0) {
            int i = n0 + wn + nt*8 + tig*2;
            atomicAdd(&g_csum[b*T_ + i],     s0);
            atomicAdd(&g_csum[b*T_ + i + 1], s1);
        }
    }
}

// ---------------- scale Vt rows by 1/colsum (uint4 = 8 bf16 per thread) ----------------
__global__ __launch_bounds__(256) void scalev_k() {
    int g = blockIdx.x * 256 + threadIdx.x;          // 0 .. BT_*C_/8-1
    int o = g * 8;
    int b = o >> 20, i = o & (T_ - 1);               // 8 consecutive t, same b-row
    const float* cs = g_csum + b*T_ + i;
    uint4 v = ((const uint4*)g_Vtb)[g];
    __nv_bfloat162* h = (__nv_bfloat162*)&v;
    #pragma unroll
    for (int u = 0; u < 4; u++) {
        float2 f = __bfloat1622float2(h[u]);
        f.x *= 1.0f / cs[u*2];
        f.y *= 1.0f / cs[u*2 + 1];
        h[u] = __floats2bfloat162_rn(f.x, f.y);
    }
    ((uint4*)g_Vtb)[g] = v;
}

// ---------------- read = P @ Vs^T (longest-first scheduling) ----------------
__global__ __launch_bounds__(NTHR, 3) void read_t(float* __restrict__ out) {
    const int tid = threadIdx.x, wid = tid >> 5, lane = tid & 31;
    const int wm = (wid >> 1) * 64, wn = (wid & 1) * 64;
    const int b = blockIdx.z;
    const int jt = 15 - blockIdx.y;                  // longest CTAs dispatch first
    const int m0 = jt * 128, n0 = blockIdx.x * 128;
    const int nk = 2 * (jt + 1);                     // BK=64 chunks; P zero beyond diag
    const __nv_bfloat16* P = g_P   + (size_t)b*T_*T_ + (size_t)m0 * T_;
    const __nv_bfloat16* V = g_Vtb + (size_t)b*C_*T_ + (size_t)n0 * T_;

    float acc[4][8][4];
    gemm_pipe(acc, nk, tid, lane, wm, wn, [=](uint32_t ad, uint32_t bd, int k) {
        ldt64(ad, P + k*64, T_, tid);
        ldt64(bd, V + k*64, T_, tid);
    });

    const int gid = lane >> 2, tig = lane & 3;
    #pragma unroll
    for (int mt = 0; mt < 4; mt++)
        #pragma unroll
        for (int nt = 0; nt < 8; nt++)
            #pragma unroll
            for (int h = 0; h < 2; h++) {
                int m = m0 + wm + mt*16 + gid + h*8;
                int n = n0 + wn + nt*8 + tig*2;
                float* orow = out + ((size_t)b * T_ + m) * 1024 + 512;
                *(float2*)(orow + n) = make_float2(acc[mt][nt][h*2+0], acc[mt][nt][h*2+1]);
            }
}

// ---------------------------------------------------------------------------
extern "C" void kernel_launch(void* const* d_in, const int* in_sizes, int n_in,
                              void* d_out, int out_size)
{
    const float* X  = (const float*)d_in[0];
    const float* Wq = (const float*)d_in[1];
    const float* bq = (const float*)d_in[2];
    const float* Wk = (const float*)d_in[3];
    const float* bk = (const float*)d_in[4];
    const float* Wv = (const float*)d_in[5];
    const float* bv = (const float*)d_in[6];
    float* out = (float*)d_out;

    cudaFuncSetAttribute(qkv_t,    cudaFuncAttributeMaxDynamicSharedMemorySize, SMEM_TOT);
    cudaFuncSetAttribute(logits_t, cudaFuncAttributeMaxDynamicSharedMemorySize, SMEM_TOT);
    cudaFuncSetAttribute(read_t,   cudaFuncAttributeMaxDynamicSharedMemorySize, SMEM_TOT);

    __nv_bfloat16* Xb; cudaGetSymbolAddress((void**)&Xb, g_Xb);
    __nv_bfloat16* Wb; cudaGetSymbolAddress((void**)&Wb, g_Wb);

    xprep_k<<<8192, 256>>>(X, out, Xb);
    wprep_k<<<dim3(256, 3), 256>>>(Wq, Wk, Wv, Wb);
    qkv_t<<<dim3(4, 128, 3), NTHR, SMEM_TOT>>>(bq, bk, bv);
    logits_t<<<dim3(136, 8), NTHR, SMEM_TOT>>>();
    scalev_k<<<4096, 256>>>();
    read_t<<<dim3(4, 16, 8), NTHR, SMEM_TOT>>>(out);
}